// round 5
// baseline (speedup 1.0000x reference)
#include <cuda_runtime.h>
#include <cuda_bf16.h>
#include <cstdint>

#define N_NODES 50000
#define D 128
#define N_EDGES 625000

// Device-global scratch (allocation-free rule; BSS zero-initialized)
__device__ __nv_bfloat16 g_W[4 * 128 * 128];   // Wl_hi, Wl_lo, Wr_hi, Wr_lo  [mat][k][n]
__device__ int g_cnt[N_NODES];                 // degree histogram (re-zeroed by aggregate)
__device__ int g_off[N_NODES + 1];             // CSR offsets (rewritten every run)
__device__ int g_cur[N_NODES];                 // permute cursors (rewritten every run)
__device__ int g_psrc[N_EDGES];                // src indices sorted by dst
__device__ __nv_bfloat16 g_mhi[N_NODES * D];   // mean, bf16 hi
__device__ __nv_bfloat16 g_mlo[N_NODES * D];   // mean, bf16 lo

// ---------------------------------------------------------------------------
// helpers
// ---------------------------------------------------------------------------
__device__ __forceinline__ uint32_t smem_u32(const void* p) {
    uint32_t a;
    asm("{ .reg .u64 t; cvta.to.shared.u64 t, %1; cvt.u32.u64 %0, t; }" : "=r"(a) : "l"(p));
    return a;
}

#define CP_ASYNC16(dst, src, sz) \
    asm volatile("cp.async.cg.shared.global [%0], [%1], 16, %2;" \
                 :: "r"(dst), "l"(src), "r"(sz))
#define CP_COMMIT() asm volatile("cp.async.commit_group;")
#define CP_WAIT0()  asm volatile("cp.async.wait_group 0;" ::: "memory")

#define LDSM_X4(r, addr) \
    asm volatile("ldmatrix.sync.aligned.m8n8.x4.shared.b16 {%0,%1,%2,%3}, [%4];" \
                 : "=r"((r)[0]), "=r"((r)[1]), "=r"((r)[2]), "=r"((r)[3]) : "r"(addr))
#define LDSM_X4T(r, addr) \
    asm volatile("ldmatrix.sync.aligned.m8n8.x4.trans.shared.b16 {%0,%1,%2,%3}, [%4];" \
                 : "=r"((r)[0]), "=r"((r)[1]), "=r"((r)[2]), "=r"((r)[3]) : "r"(addr))

__device__ __forceinline__ void mma16816(float* d, const uint32_t* a, const uint32_t* b) {
    asm volatile(
        "mma.sync.aligned.m16n8k16.row.col.f32.bf16.bf16.f32 "
        "{%0,%1,%2,%3}, {%4,%5,%6,%7}, {%8,%9}, {%0,%1,%2,%3};"
        : "+f"(d[0]), "+f"(d[1]), "+f"(d[2]), "+f"(d[3])
        : "r"(a[0]), "r"(a[1]), "r"(a[2]), "r"(a[3]), "r"(b[0]), "r"(b[1]));
}

__device__ __forceinline__ uint32_t pack_bf16x2(float a, float b) {
    __nv_bfloat16 ha = __float2bfloat16(a), hb = __float2bfloat16(b);
    return (uint32_t)__bfloat16_as_ushort(ha) | ((uint32_t)__bfloat16_as_ushort(hb) << 16);
}

// ---------------------------------------------------------------------------
// 1. prep weights: hi/lo bf16 split, [mat][k][n] row-major
// ---------------------------------------------------------------------------
__global__ void prep_weights(const float* __restrict__ Wl,
                             const float* __restrict__ Wr) {
    int idx = blockIdx.x * blockDim.x + threadIdx.x;
    if (idx >= 2 * 128 * 128) return;
    int m2 = idx >> 14;
    int k  = (idx >> 7) & 127;
    int n  = idx & 127;
    float w = (m2 ? Wr : Wl)[k * 128 + n];
    __nv_bfloat16 h = __float2bfloat16(w);
    __nv_bfloat16 l = __float2bfloat16(w - __bfloat162float(h));
    g_W[(m2 * 2 + 0) * 16384 + k * 128 + n] = h;
    g_W[(m2 * 2 + 1) * 16384 + k * 128 + n] = l;
}

// ---------------------------------------------------------------------------
// 2. histogram of destination degrees (g_cnt starts zero; re-zeroed each run)
// ---------------------------------------------------------------------------
__global__ void hist_kernel(const int* __restrict__ ei) {
    int e = blockIdx.x * blockDim.x + threadIdx.x;
    if (e < N_EDGES) atomicAdd(&g_cnt[ei[N_EDGES + e]], 1);
}

// ---------------------------------------------------------------------------
// 3. exclusive scan over 50K counts -> g_off, g_cur  (single block, 1024 thr)
// ---------------------------------------------------------------------------
#define SCAN_CHUNK 49
__global__ __launch_bounds__(1024)
void scan_kernel() {
    __shared__ int s[1024];
    int t = threadIdx.x;
    int start = t * SCAN_CHUNK;
    int end = min(start + SCAN_CHUNK, N_NODES);
    int sum = 0;
    for (int i = start; i < end; i++) sum += g_cnt[i];
    s[t] = sum;
    __syncthreads();
    #pragma unroll
    for (int off = 1; off < 1024; off <<= 1) {
        int v = s[t];
        int u = (t >= off) ? s[t - off] : 0;
        __syncthreads();
        s[t] = v + u;
        __syncthreads();
    }
    int run = s[t] - sum;       // exclusive base for this thread's chunk
    for (int i = start; i < end; i++) {
        int c = g_cnt[i];
        g_off[i] = run;
        g_cur[i] = run;
        run += c;
    }
    if (t == 0) g_off[N_NODES] = N_EDGES;
}

// ---------------------------------------------------------------------------
// 4. permute: bin src indices by dst
// ---------------------------------------------------------------------------
__global__ void permute_kernel(const int* __restrict__ ei) {
    int e = blockIdx.x * blockDim.x + threadIdx.x;
    if (e < N_EDGES) {
        int src = ei[e];
        int dst = ei[N_EDGES + e];
        int pos = atomicAdd(&g_cur[dst], 1);
        g_psrc[pos] = src;
    }
}

// ---------------------------------------------------------------------------
// 5. aggregate: one warp per node; register fp32 accumulation; write mean as
//    bf16 hi/lo; re-zero g_cnt for next replay.
// ---------------------------------------------------------------------------
__global__ __launch_bounds__(256)
void aggregate_kernel(const float* __restrict__ x) {
    int node = blockIdx.x * 8 + (threadIdx.x >> 5);
    int lane = threadIdx.x & 31;
    int start = g_off[node];
    int end   = g_off[node + 1];
    const float4* x4 = reinterpret_cast<const float4*>(x);
    float4 acc = make_float4(0.f, 0.f, 0.f, 0.f);
    for (int e = start; e < end; e += 4) {
        int s0 = g_psrc[e];
        int s1 = (e + 1 < end) ? g_psrc[e + 1] : -1;
        int s2 = (e + 2 < end) ? g_psrc[e + 2] : -1;
        int s3 = (e + 3 < end) ? g_psrc[e + 3] : -1;
        float4 v0 = x4[(size_t)s0 * 32 + lane];
        float4 v1 = (s1 >= 0) ? x4[(size_t)s1 * 32 + lane] : make_float4(0,0,0,0);
        float4 v2 = (s2 >= 0) ? x4[(size_t)s2 * 32 + lane] : make_float4(0,0,0,0);
        float4 v3 = (s3 >= 0) ? x4[(size_t)s3 * 32 + lane] : make_float4(0,0,0,0);
        acc.x += v0.x + v1.x + v2.x + v3.x;
        acc.y += v0.y + v1.y + v2.y + v3.y;
        acc.z += v0.z + v1.z + v2.z + v3.z;
        acc.w += v0.w + v1.w + v2.w + v3.w;
    }
    float invd = 1.0f / fmaxf((float)(end - start), 1.0f);
    float e0 = acc.x * invd, e1 = acc.y * invd, e2 = acc.z * invd, e3 = acc.w * invd;
    __nv_bfloat16 h0 = __float2bfloat16(e0), h1 = __float2bfloat16(e1);
    __nv_bfloat16 h2 = __float2bfloat16(e2), h3 = __float2bfloat16(e3);
    uint2 hi, lo;
    hi.x = (uint32_t)__bfloat16_as_ushort(h0) | ((uint32_t)__bfloat16_as_ushort(h1) << 16);
    hi.y = (uint32_t)__bfloat16_as_ushort(h2) | ((uint32_t)__bfloat16_as_ushort(h3) << 16);
    lo.x = pack_bf16x2(e0 - __bfloat162float(h0), e1 - __bfloat162float(h1));
    lo.y = pack_bf16x2(e2 - __bfloat162float(h2), e3 - __bfloat162float(h3));
    reinterpret_cast<uint2*>(g_mhi + (size_t)node * D)[lane] = hi;
    reinterpret_cast<uint2*>(g_mlo + (size_t)node * D)[lane] = lo;
    if (lane == 0) g_cnt[node] = 0;
}

// ---------------------------------------------------------------------------
// 6. HMMA GEMM: out = x + relu([mean|x] @ [Wl;Wr] + b)
//    64x128 tile/CTA, 2 CTAs/SM. A: m_hi/m_lo via cp.async (bf16 precomputed),
//    x_hi/x_lo converted in-kernel. bf16 hi/lo 3-term compensation.
// ---------------------------------------------------------------------------
#define ASTR 72
#define BSTR 136
#define A_MAT_B (64 * ASTR * 2)     // 9216 B
#define B_MAT_B (64 * BSTR * 2)     // 17408 B
#define SM_A_B (4 * A_MAT_B)        // 36864 B
#define SM_B_B (4 * B_MAT_B)        // 69632 B
#define SMEM_TOTAL (SM_A_B + SM_B_B)  // 106496 B -> 2 CTAs/SM

__global__ __launch_bounds__(256, 2)
void gemm_mma(const float* __restrict__ x,
              const float* __restrict__ bl,
              float* __restrict__ out) {
    extern __shared__ char sm[];
    const uint32_t sA = smem_u32(sm);
    const uint32_t sB = sA + SM_A_B;

    const int tid = threadIdx.x;
    const int lane = tid & 31;
    const int w = tid >> 5;
    const int m0 = blockIdx.x * 64;
    const int mrow0 = (w >> 1) * 16;
    const int ncol0 = (w & 1) * 64;

    float acc[8][4];
    #pragma unroll
    for (int nt = 0; nt < 8; nt++)
        #pragma unroll
        for (int q = 0; q < 4; q++) acc[nt][q] = 0.f;

    for (int c = 0; c < 2; c++) {
        const int k0 = c * 64;
        __syncthreads();    // previous chunk's MMAs done before overwrite

        // ---- B: 4 mats x 64k x 128n bf16, cp.async ----
        #pragma unroll
        for (int i = 0; i < 16; i++) {
            int idx = tid + i * 256;          // 0..4095
            int mat = idx >> 10;
            int rem = idx & 1023;
            int r = rem >> 4, sg = rem & 15;
            uint32_t dst = sB + mat * B_MAT_B + r * (BSTR * 2) + sg * 16;
            const void* src = g_W + mat * 16384 + (k0 + r) * 128 + sg * 8;
            CP_ASYNC16(dst, src, 16);
        }
        // ---- A mean mats: 2 x 64rows x 64cols bf16, cp.async (oob -> zero-fill) ----
        #pragma unroll
        for (int i = 0; i < 4; i++) {
            int idx = tid + i * 256;          // 0..1023
            int mat = idx >> 9;               // 0: hi, 1: lo
            int rem = idx & 511;
            int r = rem >> 3, sg = rem & 7;
            int row = m0 + r;
            bool valid = row < N_NODES;
            uint32_t dst = sA + mat * A_MAT_B + r * (ASTR * 2) + sg * 16;
            const __nv_bfloat16* base = mat ? g_mlo : g_mhi;
            const void* src = valid ? (const void*)(base + (size_t)row * D + k0 + sg * 8)
                                    : (const void*)base;
            CP_ASYNC16(dst, src, valid ? 16 : 0);
        }
        CP_COMMIT();

        // ---- A x mats: convert fp32 -> bf16 hi/lo (4 threads per row) ----
        {
            int r = tid >> 2;                 // 0..63
            int part = tid & 3;               // 16 cols each
            int row = m0 + r;
            bool valid = row < N_NODES;
            const float4* src = reinterpret_cast<const float4*>(
                x + (size_t)row * D + k0 + part * 16);
            uint32_t hi[8], lo[8];
            #pragma unroll
            for (int i = 0; i < 4; i++) {
                float4 v = valid ? src[i] : make_float4(0.f, 0.f, 0.f, 0.f);
                __nv_bfloat16 h0 = __float2bfloat16(v.x), h1 = __float2bfloat16(v.y);
                __nv_bfloat16 h2 = __float2bfloat16(v.z), h3 = __float2bfloat16(v.w);
                hi[2*i]   = (uint32_t)__bfloat16_as_ushort(h0) | ((uint32_t)__bfloat16_as_ushort(h1) << 16);
                hi[2*i+1] = (uint32_t)__bfloat16_as_ushort(h2) | ((uint32_t)__bfloat16_as_ushort(h3) << 16);
                lo[2*i]   = pack_bf16x2(v.x - __bfloat162float(h0), v.y - __bfloat162float(h1));
                lo[2*i+1] = pack_bf16x2(v.z - __bfloat162float(h2), v.w - __bfloat162float(h3));
            }
            uint4* dh = reinterpret_cast<uint4*>(sm + 2 * A_MAT_B + r * (ASTR * 2) + part * 32);
            uint4* dl = reinterpret_cast<uint4*>(sm + 3 * A_MAT_B + r * (ASTR * 2) + part * 32);
            dh[0] = make_uint4(hi[0], hi[1], hi[2], hi[3]);
            dh[1] = make_uint4(hi[4], hi[5], hi[6], hi[7]);
            dl[0] = make_uint4(lo[0], lo[1], lo[2], lo[3]);
            dl[1] = make_uint4(lo[4], lo[5], lo[6], lo[7]);
        }
        CP_WAIT0();
        __syncthreads();

        // ---- MMA mainloop: 4 k16-steps ----
        #pragma unroll
        for (int ks = 0; ks < 4; ks++) {
            const int kk = ks * 16;
            uint32_t a[4][4];
            #pragma unroll
            for (int mat = 0; mat < 4; mat++) {
                uint32_t addr = sA + mat * A_MAT_B
                              + (mrow0 + (lane & 15)) * (ASTR * 2)
                              + (kk + ((lane >> 4) * 8)) * 2;
                LDSM_X4(a[mat], addr);
            }
            #pragma unroll
            for (int np = 0; np < 4; np++) {
                const int ncol = ncol0 + np * 16;
                uint32_t b[4][4];
                #pragma unroll
                for (int mat = 0; mat < 4; mat++) {
                    int quad = lane >> 3;
                    uint32_t addr = sB + mat * B_MAT_B
                                  + (kk + (quad & 1) * 8 + (lane & 7)) * (BSTR * 2)
                                  + (ncol + (quad >> 1) * 8) * 2;
                    LDSM_X4T(b[mat], addr);
                }
                #pragma unroll
                for (int nt = 0; nt < 2; nt++) {
                    float* d = acc[np * 2 + nt];
                    mma16816(d, a[0], b[0] + nt * 2);   // m_hi * Wl_hi
                    mma16816(d, a[1], b[0] + nt * 2);   // m_lo * Wl_hi
                    mma16816(d, a[0], b[1] + nt * 2);   // m_hi * Wl_lo
                    mma16816(d, a[2], b[2] + nt * 2);   // x_hi * Wr_hi
                    mma16816(d, a[3], b[2] + nt * 2);   // x_lo * Wr_hi
                    mma16816(d, a[2], b[3] + nt * 2);   // x_hi * Wr_lo
                }
            }
        }
    }

    // ---- epilogue: out = x + relu(acc + b) ----
    const int rq = lane >> 2;
    const int cq = (lane & 3) * 2;
    #pragma unroll
    for (int h = 0; h < 2; h++) {
        int row = m0 + mrow0 + h * 8 + rq;
        if (row < N_NODES) {
            #pragma unroll
            for (int nt = 0; nt < 8; nt++) {
                int col = ncol0 + nt * 8 + cq;
                float d0 = acc[nt][h * 2 + 0];
                float d1 = acc[nt][h * 2 + 1];
                float2 bv = *reinterpret_cast<const float2*>(bl + col);
                float2 xv = *reinterpret_cast<const float2*>(x + (size_t)row * D + col);
                float2 o;
                o.x = xv.x + fmaxf(d0 + bv.x, 0.f);
                o.y = xv.y + fmaxf(d1 + bv.y, 0.f);
                *reinterpret_cast<float2*>(out + (size_t)row * D + col) = o;
            }
        }
    }
}

// ---------------------------------------------------------------------------
// launch
// ---------------------------------------------------------------------------
extern "C" void kernel_launch(void* const* d_in, const int* in_sizes, int n_in,
                              void* d_out, int out_size) {
    const float* x  = (const float*)d_in[0];
    const int*   ei = (const int*)d_in[1];
    const float* Wl = (const float*)d_in[2];
    const float* bl = (const float*)d_in[3];
    const float* Wr = (const float*)d_in[4];
    float* out = (float*)d_out;
    (void)in_sizes; (void)n_in; (void)out_size;

    prep_weights<<<(2 * 128 * 128 + 255) / 256, 256>>>(Wl, Wr);
    hist_kernel<<<(N_EDGES + 255) / 256, 256>>>(ei);
    scan_kernel<<<1, 1024>>>();
    permute_kernel<<<(N_EDGES + 255) / 256, 256>>>(ei);
    aggregate_kernel<<<N_NODES / 8, 256>>>(x);

    cudaFuncSetAttribute(gemm_mma, cudaFuncAttributeMaxDynamicSharedMemorySize,
                         SMEM_TOTAL);
    gemm_mma<<<(N_NODES + 63) / 64, 256, SMEM_TOTAL>>>(x, bl, out);
}

// round 6
// speedup vs baseline: 1.3304x; 1.3304x over previous
#include <cuda_runtime.h>
#include <cuda_bf16.h>
#include <cstdint>

#define N_NODES 50000
#define D 128
#define N_EDGES 625000

// Device-global scratch (allocation-free rule; BSS zero-initialized)
__device__ float g_sum[N_NODES * D];          // re-zeroed by gemm each run
__device__ float g_deg[N_NODES];              // re-zeroed by inv each run
__device__ float g_inv[N_NODES];
__device__ __nv_bfloat16 g_W[4 * 128 * 128];  // Wl_hi, Wl_lo, Wr_hi, Wr_lo  [mat][k][n]

// ---------------------------------------------------------------------------
// helpers
// ---------------------------------------------------------------------------
__device__ __forceinline__ uint32_t smem_u32(const void* p) {
    uint32_t a;
    asm("{ .reg .u64 t; cvta.to.shared.u64 t, %1; cvt.u32.u64 %0, t; }" : "=r"(a) : "l"(p));
    return a;
}

#define CP_ASYNC16(dst, src) \
    asm volatile("cp.async.cg.shared.global [%0], [%1], 16;" :: "r"(dst), "l"(src))
#define CP_COMMIT() asm volatile("cp.async.commit_group;")
#define CP_WAIT0()  asm volatile("cp.async.wait_group 0;" ::: "memory")

#define LDSM_X4(r, addr) \
    asm volatile("ldmatrix.sync.aligned.m8n8.x4.shared.b16 {%0,%1,%2,%3}, [%4];" \
                 : "=r"((r)[0]), "=r"((r)[1]), "=r"((r)[2]), "=r"((r)[3]) : "r"(addr))
#define LDSM_X4T(r, addr) \
    asm volatile("ldmatrix.sync.aligned.m8n8.x4.trans.shared.b16 {%0,%1,%2,%3}, [%4];" \
                 : "=r"((r)[0]), "=r"((r)[1]), "=r"((r)[2]), "=r"((r)[3]) : "r"(addr))

__device__ __forceinline__ void mma16816(float* d, const uint32_t* a, const uint32_t* b) {
    asm volatile(
        "mma.sync.aligned.m16n8k16.row.col.f32.bf16.bf16.f32 "
        "{%0,%1,%2,%3}, {%4,%5,%6,%7}, {%8,%9}, {%0,%1,%2,%3};"
        : "+f"(d[0]), "+f"(d[1]), "+f"(d[2]), "+f"(d[3])
        : "r"(a[0]), "r"(a[1]), "r"(a[2]), "r"(a[3]), "r"(b[0]), "r"(b[1]));
}

__device__ __forceinline__ uint32_t pack_bf16x2(float a, float b) {
    __nv_bfloat16 ha = __float2bfloat16(a), hb = __float2bfloat16(b);
    return (uint32_t)__bfloat16_as_ushort(ha) | ((uint32_t)__bfloat16_as_ushort(hb) << 16);
}

// ---------------------------------------------------------------------------
// 1. prep weights: hi/lo bf16 split, [mat][k][n] row-major
// ---------------------------------------------------------------------------
__global__ void prep_weights(const float* __restrict__ Wl,
                             const float* __restrict__ Wr) {
    int idx = blockIdx.x * blockDim.x + threadIdx.x;
    if (idx >= 2 * 128 * 128) return;
    int m2 = idx >> 14;
    int k  = (idx >> 7) & 127;
    int n  = idx & 127;
    float w = (m2 ? Wr : Wl)[k * 128 + n];
    __nv_bfloat16 h = __float2bfloat16(w);
    __nv_bfloat16 l = __float2bfloat16(w - __bfloat162float(h));
    g_W[(m2 * 2 + 0) * 16384 + k * 128 + n] = h;
    g_W[(m2 * 2 + 1) * 16384 + k * 128 + n] = l;
}

// ---------------------------------------------------------------------------
// 2. edge scatter: one warp per edge, red.global.add.v4.f32 (L2-atomic bound)
// ---------------------------------------------------------------------------
__global__ void scatter_kernel(const float* __restrict__ x,
                               const int* __restrict__ ei) {
    int warp = (blockIdx.x * blockDim.x + threadIdx.x) >> 5;
    int lane = threadIdx.x & 31;
    if (warp >= N_EDGES) return;
    int src = ei[warp];
    int dst = ei[N_EDGES + warp];
    const float4* xr = reinterpret_cast<const float4*>(x + (size_t)src * D);
    float4 v = xr[lane];
    float* dptr = g_sum + (size_t)dst * D + lane * 4;
    asm volatile("red.global.add.v4.f32 [%0], {%1, %2, %3, %4};"
                 :: "l"(dptr), "f"(v.x), "f"(v.y), "f"(v.z), "f"(v.w)
                 : "memory");
    if (lane == 0) atomicAdd(g_deg + dst, 1.0f);
}

// ---------------------------------------------------------------------------
// 3. inverse degree; re-zeroes g_deg for the next replay
// ---------------------------------------------------------------------------
__global__ void inv_kernel() {
    int i = blockIdx.x * blockDim.x + threadIdx.x;
    if (i < N_NODES) {
        float d = g_deg[i];
        g_inv[i] = 1.0f / fmaxf(d, 1.0f);
        g_deg[i] = 0.0f;
    }
}

// ---------------------------------------------------------------------------
// 4. HMMA GEMM: out = x + relu([mean|x] @ [Wl;Wr] + b)
//    64x128 tile/CTA, 2 CTAs/SM. bf16 hi/lo 3-term compensation.
//    B via cp.async; mean (g_sum*g_inv) and x converted in-kernel.
//    Re-zeroes g_sum after reading (no separate zero kernel).
// ---------------------------------------------------------------------------
#define ASTR 72
#define BSTR 136
#define A_MAT_B (64 * ASTR * 2)       // 9216 B
#define B_MAT_B (64 * BSTR * 2)       // 17408 B
#define SM_A_B (4 * A_MAT_B)          // 36864 B
#define SM_B_B (4 * B_MAT_B)          // 69632 B
#define SMEM_TOTAL (SM_A_B + SM_B_B)  // 106496 B -> 2 CTAs/SM

__global__ __launch_bounds__(256, 2)
void gemm_mma(const float* __restrict__ x,
              const float* __restrict__ bl,
              float* __restrict__ out) {
    extern __shared__ char sm[];
    const uint32_t sA = smem_u32(sm);
    const uint32_t sB = sA + SM_A_B;

    const int tid = threadIdx.x;
    const int lane = tid & 31;
    const int w = tid >> 5;
    const int m0 = blockIdx.x * 64;
    const int mrow0 = (w >> 1) * 16;
    const int ncol0 = (w & 1) * 64;

    float acc[8][4];
    #pragma unroll
    for (int nt = 0; nt < 8; nt++)
        #pragma unroll
        for (int q = 0; q < 4; q++) acc[nt][q] = 0.f;

    for (int c = 0; c < 2; c++) {
        const int k0 = c * 64;
        __syncthreads();    // previous chunk's MMAs done before smem overwrite

        // ---- B: 4 mats x 64k x 128n bf16 via cp.async ----
        #pragma unroll
        for (int i = 0; i < 16; i++) {
            int idx = tid + i * 256;          // 0..4095
            int mat = idx >> 10;
            int rem = idx & 1023;
            int r = rem >> 4, sg = rem & 15;
            uint32_t dst = sB + mat * B_MAT_B + r * (BSTR * 2) + sg * 16;
            const void* src = g_W + mat * 16384 + (k0 + r) * 128 + sg * 8;
            CP_ASYNC16(dst, src);
        }
        CP_COMMIT();

        // ---- A conversion: 4 threads per row, 16 cols each ----
        {
            int r = tid >> 2;                 // 0..63
            int part = tid & 3;
            int row = m0 + r;
            bool valid = row < N_NODES;
            float invd = valid ? g_inv[row] : 1.0f;

            // mean mats (0: hi, 1: lo) from g_sum * invd; re-zero after read
            float4* ms = valid
                ? reinterpret_cast<float4*>(g_sum + (size_t)row * D + k0 + part * 16)
                : nullptr;
            uint32_t hi[8], lo[8];
            #pragma unroll
            for (int i = 0; i < 4; i++) {
                float4 v = valid ? ms[i] : make_float4(0.f, 0.f, 0.f, 0.f);
                float e0 = v.x * invd, e1 = v.y * invd, e2 = v.z * invd, e3 = v.w * invd;
                __nv_bfloat16 h0 = __float2bfloat16(e0), h1 = __float2bfloat16(e1);
                __nv_bfloat16 h2 = __float2bfloat16(e2), h3 = __float2bfloat16(e3);
                hi[2*i]   = (uint32_t)__bfloat16_as_ushort(h0) | ((uint32_t)__bfloat16_as_ushort(h1) << 16);
                hi[2*i+1] = (uint32_t)__bfloat16_as_ushort(h2) | ((uint32_t)__bfloat16_as_ushort(h3) << 16);
                lo[2*i]   = pack_bf16x2(e0 - __bfloat162float(h0), e1 - __bfloat162float(h1));
                lo[2*i+1] = pack_bf16x2(e2 - __bfloat162float(h2), e3 - __bfloat162float(h3));
            }
            {
                uint4* dh = reinterpret_cast<uint4*>(sm + 0 * A_MAT_B + r * (ASTR * 2) + part * 32);
                uint4* dl = reinterpret_cast<uint4*>(sm + 1 * A_MAT_B + r * (ASTR * 2) + part * 32);
                dh[0] = make_uint4(hi[0], hi[1], hi[2], hi[3]);
                dh[1] = make_uint4(hi[4], hi[5], hi[6], hi[7]);
                dl[0] = make_uint4(lo[0], lo[1], lo[2], lo[3]);
                dl[1] = make_uint4(lo[4], lo[5], lo[6], lo[7]);
            }
            if (valid) {
                float4 zz = make_float4(0.f, 0.f, 0.f, 0.f);
                #pragma unroll
                for (int i = 0; i < 4; i++) ms[i] = zz;
            }

            // x mats (2: hi, 3: lo)
            const float4* xs = reinterpret_cast<const float4*>(
                x + (size_t)row * D + k0 + part * 16);
            #pragma unroll
            for (int i = 0; i < 4; i++) {
                float4 v = valid ? xs[i] : make_float4(0.f, 0.f, 0.f, 0.f);
                __nv_bfloat16 h0 = __float2bfloat16(v.x), h1 = __float2bfloat16(v.y);
                __nv_bfloat16 h2 = __float2bfloat16(v.z), h3 = __float2bfloat16(v.w);
                hi[2*i]   = (uint32_t)__bfloat16_as_ushort(h0) | ((uint32_t)__bfloat16_as_ushort(h1) << 16);
                hi[2*i+1] = (uint32_t)__bfloat16_as_ushort(h2) | ((uint32_t)__bfloat16_as_ushort(h3) << 16);
                lo[2*i]   = pack_bf16x2(v.x - __bfloat162float(h0), v.y - __bfloat162float(h1));
                lo[2*i+1] = pack_bf16x2(v.z - __bfloat162float(h2), v.w - __bfloat162float(h3));
            }
            {
                uint4* dh = reinterpret_cast<uint4*>(sm + 2 * A_MAT_B + r * (ASTR * 2) + part * 32);
                uint4* dl = reinterpret_cast<uint4*>(sm + 3 * A_MAT_B + r * (ASTR * 2) + part * 32);
                dh[0] = make_uint4(hi[0], hi[1], hi[2], hi[3]);
                dh[1] = make_uint4(hi[4], hi[5], hi[6], hi[7]);
                dl[0] = make_uint4(lo[0], lo[1], lo[2], lo[3]);
                dl[1] = make_uint4(lo[4], lo[5], lo[6], lo[7]);
            }
        }
        CP_WAIT0();
        __syncthreads();

        // ---- MMA mainloop: 4 k16-steps ----
        #pragma unroll
        for (int ks = 0; ks < 4; ks++) {
            const int kk = ks * 16;
            uint32_t a[4][4];
            #pragma unroll
            for (int mat = 0; mat < 4; mat++) {
                uint32_t addr = sA + mat * A_MAT_B
                              + (mrow0 + (lane & 15)) * (ASTR * 2)
                              + (kk + ((lane >> 4) * 8)) * 2;
                LDSM_X4(a[mat], addr);
            }
            #pragma unroll
            for (int np = 0; np < 4; np++) {
                const int ncol = ncol0 + np * 16;
                uint32_t b[4][4];
                #pragma unroll
                for (int mat = 0; mat < 4; mat++) {
                    int quad = lane >> 3;
                    uint32_t addr = sB + mat * B_MAT_B
                                  + (kk + (quad & 1) * 8 + (lane & 7)) * (BSTR * 2)
                                  + (ncol + (quad >> 1) * 8) * 2;
                    LDSM_X4T(b[mat], addr);
                }
                #pragma unroll
                for (int nt = 0; nt < 2; nt++) {
                    float* d = acc[np * 2 + nt];
                    mma16816(d, a[0], b[0] + nt * 2);   // m_hi * Wl_hi
                    mma16816(d, a[1], b[0] + nt * 2);   // m_lo * Wl_hi
                    mma16816(d, a[0], b[1] + nt * 2);   // m_hi * Wl_lo
                    mma16816(d, a[2], b[2] + nt * 2);   // x_hi * Wr_hi
                    mma16816(d, a[3], b[2] + nt * 2);   // x_lo * Wr_hi
                    mma16816(d, a[2], b[3] + nt * 2);   // x_hi * Wr_lo
                }
            }
        }
    }

    // ---- epilogue: out = x + relu(acc + b) ----
    const int rq = lane >> 2;
    const int cq = (lane & 3) * 2;
    #pragma unroll
    for (int h = 0; h < 2; h++) {
        int row = m0 + mrow0 + h * 8 + rq;
        if (row < N_NODES) {
            #pragma unroll
            for (int nt = 0; nt < 8; nt++) {
                int col = ncol0 + nt * 8 + cq;
                float d0 = acc[nt][h * 2 + 0];
                float d1 = acc[nt][h * 2 + 1];
                float2 bv = *reinterpret_cast<const float2*>(bl + col);
                float2 xv = *reinterpret_cast<const float2*>(x + (size_t)row * D + col);
                float2 o;
                o.x = xv.x + fmaxf(d0 + bv.x, 0.f);
                o.y = xv.y + fmaxf(d1 + bv.y, 0.f);
                *reinterpret_cast<float2*>(out + (size_t)row * D + col) = o;
            }
        }
    }
}

// ---------------------------------------------------------------------------
// launch
// ---------------------------------------------------------------------------
extern "C" void kernel_launch(void* const* d_in, const int* in_sizes, int n_in,
                              void* d_out, int out_size) {
    const float* x  = (const float*)d_in[0];
    const int*   ei = (const int*)d_in[1];
    const float* Wl = (const float*)d_in[2];
    const float* bl = (const float*)d_in[3];
    const float* Wr = (const float*)d_in[4];
    float* out = (float*)d_out;
    (void)in_sizes; (void)n_in; (void)out_size;

    // 1. weight prep (hi/lo bf16 split)
    prep_weights<<<(2 * 128 * 128 + 255) / 256, 256>>>(Wl, Wr);

    // 2. edge scatter (1 warp per edge; g_sum zeroed by previous gemm / BSS init)
    scatter_kernel<<<(N_EDGES * 32 + 255) / 256, 256>>>(x, ei);

    // 3. inverse degree (re-zeroes g_deg)
    inv_kernel<<<(N_NODES + 255) / 256, 256>>>();

    // 4. HMMA dual GEMM + bias + relu + residual (re-zeroes g_sum)
    cudaFuncSetAttribute(gemm_mma, cudaFuncAttributeMaxDynamicSharedMemorySize,
                         SMEM_TOTAL);
    gemm_mma<<<(N_NODES + 63) / 64, 256, SMEM_TOTAL>>>(x, bl, out);
}